// round 5
// baseline (speedup 1.0000x reference)
#include <cuda_runtime.h>
#include <math.h>

#define BSZ   2
#define CDIM  256
#define LDIM  4096
#define HEADS 8
#define HD    32
#define N3C   768

__device__ float g_q[BSZ*HEADS*LDIM*HD];
__device__ float g_k[BSZ*HEADS*LDIM*HD];
__device__ float g_v[BSZ*HEADS*LDIM*HD];
__device__ float g_o[BSZ*LDIM*CDIM];

__device__ __forceinline__ unsigned f2tf(float f) {
    unsigned r;
    asm("cvt.rna.tf32.f32 %0, %1;" : "=r"(r) : "f"(f));
    return r;
}

__device__ __forceinline__ void mma8(float* c, const unsigned* a, const unsigned* b) {
    asm volatile(
        "mma.sync.aligned.m16n8k8.row.col.f32.tf32.tf32.f32 "
        "{%0,%1,%2,%3},{%4,%5,%6,%7},{%8,%9},{%0,%1,%2,%3};"
        : "+f"(c[0]), "+f"(c[1]), "+f"(c[2]), "+f"(c[3])
        : "r"(a[0]), "r"(a[1]), "r"(a[2]), "r"(a[3]), "r"(b[0]), "r"(b[1]));
}

__device__ __forceinline__ void st_tf4(unsigned* dst, float4 v) {
    unsigned u[4] = {f2tf(v.x), f2tf(v.y), f2tf(v.z), f2tf(v.w)};
    *(uint4*)dst = *(uint4*)u;
}

// ---------------------------------------------------------------------------
// Kernel 1: qkv via tf32 mma, operand-swapped: C^T[n][m] = w1^T[n][k] * x[k][m]
// Pipelined: single register buffer, LDG of chunk t+1 overlaps compute of t.
// ---------------------------------------------------------------------------
__global__ void __launch_bounds__(256) qkv_gemm(const float* __restrict__ x,
                                                const float* __restrict__ w1,
                                                const float* __restrict__ b1) {
    __shared__ unsigned Ws[32][72];   // [k][n]  (tf32 bits)
    __shared__ unsigned Xs[32][72];   // [k][m]

    const int b  = blockIdx.z;
    const int m0 = blockIdx.x * 64;
    const int n0 = blockIdx.y * 64;
    const int t  = threadIdx.x;
    const int lane = t & 31;
    const int warp = t >> 5;
    const int wr = warp >> 1;
    const int wc = warp & 1;
    const int g  = lane >> 2;
    const int tg = lane & 3;

    const float* xb = x + (size_t)b * CDIM * LDIM;
    float acc[4][4] = {};

    // per-thread staging coords
    const int s_kk = t >> 4, s_c4 = (t & 15) * 4;          // p=0
    const int s_kk2 = s_kk + 16;                            // p=1

    float4 wR[2], xR[2];
    wR[0] = *(const float4*)&w1[(size_t)s_kk  * N3C + n0 + s_c4];
    wR[1] = *(const float4*)&w1[(size_t)s_kk2 * N3C + n0 + s_c4];
    xR[0] = *(const float4*)&xb[(size_t)s_kk  * LDIM + m0 + s_c4];
    xR[1] = *(const float4*)&xb[(size_t)s_kk2 * LDIM + m0 + s_c4];

    for (int k0 = 0; k0 < CDIM; k0 += 32) {
        __syncthreads();
        st_tf4(&Ws[s_kk][s_c4],  wR[0]);
        st_tf4(&Ws[s_kk2][s_c4], wR[1]);
        st_tf4(&Xs[s_kk][s_c4],  xR[0]);
        st_tf4(&Xs[s_kk2][s_c4], xR[1]);
        if (k0 + 32 < CDIM) {
            int kn = k0 + 32;
            wR[0] = *(const float4*)&w1[(size_t)(kn + s_kk)  * N3C + n0 + s_c4];
            wR[1] = *(const float4*)&w1[(size_t)(kn + s_kk2) * N3C + n0 + s_c4];
            xR[0] = *(const float4*)&xb[(size_t)(kn + s_kk)  * LDIM + m0 + s_c4];
            xR[1] = *(const float4*)&xb[(size_t)(kn + s_kk2) * LDIM + m0 + s_c4];
        }
        __syncthreads();

        unsigned af[4][4];
        #pragma unroll
        for (int ks = 0; ks < 4; ks++) {
            af[ks][0] = Ws[ks * 8 + tg][wr * 16 + g];
            af[ks][1] = Ws[ks * 8 + tg][wr * 16 + g + 8];
            af[ks][2] = Ws[ks * 8 + tg + 4][wr * 16 + g];
            af[ks][3] = Ws[ks * 8 + tg + 4][wr * 16 + g + 8];
        }
        #pragma unroll
        for (int mb = 0; mb < 4; mb++) {
            int mc = wc * 32 + mb * 8 + g;
            #pragma unroll
            for (int ks = 0; ks < 4; ks++) {
                unsigned bf[2] = {Xs[ks * 8 + tg][mc], Xs[ks * 8 + tg + 4][mc]};
                mma8(acc[mb], af[ks], bf);
            }
        }
    }

    const float inv_scale = 0.1767766952966368811f;  // 1/sqrt(32)
    const int n_r0 = n0 + wr * 16 + g;
    const int n_r1 = n_r0 + 8;
    // hoist channel decomposition (2 n values per thread)
    const int k3_0 = n_r0 % 3, h_0 = (n_r0 / 3) & 7, c_0 = n_r0 / 24;
    const int k3_1 = n_r1 % 3, h_1 = (n_r1 / 3) & 7, c_1 = n_r1 / 24;
    const float bias0 = b1[n_r0], bias1 = b1[n_r1];
    float* dst0 = (k3_0 == 0) ? g_q : (k3_0 == 1) ? g_k : g_v;
    float* dst1 = (k3_1 == 0) ? g_q : (k3_1 == 1) ? g_k : g_v;
    const float sc0 = (k3_0 == 0) ? inv_scale : 1.f;
    const float sc1 = (k3_1 == 0) ? inv_scale : 1.f;
    const size_t base0 = (size_t)(b * HEADS + h_0) * LDIM;
    const size_t base1 = (size_t)(b * HEADS + h_1) * LDIM;
    #pragma unroll
    for (int mb = 0; mb < 4; mb++) {
        int mA = m0 + wc * 32 + mb * 8 + 2 * tg;
        dst0[(base0 + mA)     * HD + c_0] = (acc[mb][0] + bias0) * sc0;
        dst0[(base0 + mA + 1) * HD + c_0] = (acc[mb][1] + bias0) * sc0;
        dst1[(base1 + mA)     * HD + c_1] = (acc[mb][2] + bias1) * sc1;
        dst1[(base1 + mA + 1) * HD + c_1] = (acc[mb][3] + bias1) * sc1;
    }
}

// ---------------------------------------------------------------------------
// Kernel 2: banded attention via tf32 mma.sync; pipelined K/V staging.
// ---------------------------------------------------------------------------
__global__ void __launch_bounds__(256) attn_kernel() {
    __shared__ unsigned Qs[64][36];
    __shared__ unsigned Ks[64][36];
    __shared__ unsigned Vs[64][40];
    __shared__ unsigned Ps[64][68];
    __shared__ float    Lsm[64][2];

    const int qt = blockIdx.x;
    const int bh = blockIdx.y;
    const int i0 = qt * 64;
    const int t  = threadIdx.x;
    const int lane = t & 31;
    const int warp = t >> 5;
    const int wr = warp >> 1;
    const int wc = warp & 1;
    const int g  = lane >> 2;
    const int tg = lane & 3;

    const float* qb = g_q + (size_t)bh * LDIM * HD;
    const float* kb = g_k + (size_t)bh * LDIM * HD;
    const float* vb = g_v + (size_t)bh * LDIM * HD;

    // staging coords (per thread, 2 rows)
    const int s_row0 = t >> 3, s_c4 = (t & 7) * 4;
    const int s_row1 = s_row0 + 32;

    // stage Q
    st_tf4(&Qs[s_row0][s_c4], *(const float4*)&qb[(size_t)(i0 + s_row0) * HD + s_c4]);
    st_tf4(&Qs[s_row1][s_c4], *(const float4*)&qb[(size_t)(i0 + s_row1) * HD + s_c4]);

    // tile sequence (closed form, uniform across block)
    const bool hasG = (qt == 0) || (qt == 63);
    const int  tlo  = max(0, i0 - 512) >> 6;
    const int  thi  = min(LDIM - 1, i0 + 63 + 512) >> 6;
    const int  lead  = (tlo > 0) ? 1 : 0;
    const int  trail = (thi < 63) ? 1 : 0;
    const int  nband = thi - tlo + 1;
    const int  cnt   = hasG ? 64 : (nband + lead + trail);

    // prologue: load first tile into regs
    int t0 = hasG ? 0 : (lead ? 0 : tlo);
    float4 kR[2], vR[2];
    {
        const int j0 = t0 * 64;
        kR[0] = *(const float4*)&kb[(size_t)(j0 + s_row0) * HD + s_c4];
        kR[1] = *(const float4*)&kb[(size_t)(j0 + s_row1) * HD + s_c4];
        vR[0] = *(const float4*)&vb[(size_t)(j0 + s_row0) * HD + s_c4];
        vR[1] = *(const float4*)&vb[(size_t)(j0 + s_row1) * HD + s_c4];
    }
    __syncthreads();

    unsigned af[4][4];
    const int r0 = wr * 16 + g;
    const int r1 = r0 + 8;
    #pragma unroll
    for (int ks = 0; ks < 4; ks++) {
        af[ks][0] = Qs[r0][ks * 8 + tg];
        af[ks][1] = Qs[r1][ks * 8 + tg];
        af[ks][2] = Qs[r0][ks * 8 + tg + 4];
        af[ks][3] = Qs[r1][ks * 8 + tg + 4];
    }

    const int ir0 = i0 + r0, ir1 = i0 + r1;
    const bool ig0 = (ir0 == 0) || (ir0 == 63) || (ir0 == 4032) || (ir0 == 4095);
    const bool ig1 = (ir1 == 0) || (ir1 == 63) || (ir1 == 4032) || (ir1 == 4095);

    float oacc[2][4] = {};
    float ls0 = 0.f, ls1 = 0.f;
    int tcur = t0;

    for (int it = 0; it < cnt; it++) {
        const int j0 = tcur * 64;

        __syncthreads();                       // prev PV done: Ks/Vs free
        st_tf4(&Ks[s_row0][s_c4], kR[0]);
        st_tf4(&Ks[s_row1][s_c4], kR[1]);
        st_tf4(&Vs[s_row0][s_c4], vR[0]);
        st_tf4(&Vs[s_row1][s_c4], vR[1]);
        if (it + 1 < cnt) {
            // next tile index (closed form)
            int nx = it + 1;
            int tnext;
            if (hasG) tnext = nx;
            else {
                int j = nx - lead;
                tnext = (nx == 0 && lead) ? 0 : ((j < nband) ? (tlo + j) : 63);
            }
            const int jn = tnext * 64;
            kR[0] = *(const float4*)&kb[(size_t)(jn + s_row0) * HD + s_c4];
            kR[1] = *(const float4*)&kb[(size_t)(jn + s_row1) * HD + s_c4];
            vR[0] = *(const float4*)&vb[(size_t)(jn + s_row0) * HD + s_c4];
            vR[1] = *(const float4*)&vb[(size_t)(jn + s_row1) * HD + s_c4];
            tcur = tnext;
        }
        __syncthreads();

        // S = Q @ K^T
        float sacc[4][4] = {};
        #pragma unroll
        for (int nb = 0; nb < 4; nb++) {
            int jn = wc * 32 + nb * 8 + g;
            #pragma unroll
            for (int ks = 0; ks < 4; ks++) {
                unsigned bf[2] = {Ks[jn][ks * 8 + tg], Ks[jn][ks * 8 + tg + 4]};
                mma8(sacc[nb], af[ks], bf);
            }
        }

        // mask + exp + store P
        #pragma unroll
        for (int nb = 0; nb < 4; nb++) {
            int jb = j0 + wc * 32 + nb * 8 + 2 * tg;
            int jb1 = jb + 1;
            bool jg0 = (jb == 0) || (jb == 63) || (jb == 4032) || (jb == 4095);
            bool jg1 = (jb1 == 0) || (jb1 == 63) || (jb1 == 4032) || (jb1 == 4095);
            int d00 = ir0 - jb, d01 = ir0 - jb1, d10 = ir1 - jb, d11 = ir1 - jb1;
            float p0 = (ig0 || jg0 || (d00 <= 512 && d00 >= -512)) ? __expf(sacc[nb][0]) : 0.f;
            float p1 = (ig0 || jg1 || (d01 <= 512 && d01 >= -512)) ? __expf(sacc[nb][1]) : 0.f;
            float p2 = (ig1 || jg0 || (d10 <= 512 && d10 >= -512)) ? __expf(sacc[nb][2]) : 0.f;
            float p3 = (ig1 || jg1 || (d11 <= 512 && d11 >= -512)) ? __expf(sacc[nb][3]) : 0.f;
            unsigned u0 = f2tf(p0), u1 = f2tf(p1), u2 = f2tf(p2), u3 = f2tf(p3);
            ls0 += __uint_as_float(u0) + __uint_as_float(u1);
            ls1 += __uint_as_float(u2) + __uint_as_float(u3);
            int colb = wc * 32 + nb * 8 + 2 * tg;
            uint2 w0 = {u0, u1}, w1v = {u2, u3};
            *(uint2*)&Ps[r0][colb] = w0;
            *(uint2*)&Ps[r1][colb] = w1v;
        }
        __syncthreads();

        // O += P @ V
        #pragma unroll
        for (int ks = 0; ks < 8; ks++) {
            unsigned pa[4] = {Ps[r0][ks * 8 + tg],     Ps[r1][ks * 8 + tg],
                              Ps[r0][ks * 8 + tg + 4], Ps[r1][ks * 8 + tg + 4]};
            #pragma unroll
            for (int nb = 0; nb < 2; nb++) {
                int cn = wc * 16 + nb * 8 + g;
                unsigned vf[2] = {Vs[ks * 8 + tg][cn], Vs[ks * 8 + tg + 4][cn]};
                mma8(oacc[nb], pa, vf);
            }
        }
    }

    ls0 += __shfl_xor_sync(~0u, ls0, 1); ls0 += __shfl_xor_sync(~0u, ls0, 2);
    ls1 += __shfl_xor_sync(~0u, ls1, 1); ls1 += __shfl_xor_sync(~0u, ls1, 2);
    if (tg == 0) { Lsm[r0][wc] = ls0; Lsm[r1][wc] = ls1; }
    __syncthreads();
    float inv0 = 1.f / (Lsm[r0][0] + Lsm[r0][1]);
    float inv1 = 1.f / (Lsm[r1][0] + Lsm[r1][1]);

    const int b = bh >> 3, h = bh & 7;
    #pragma unroll
    for (int nb = 0; nb < 2; nb++) {
        int c0 = wc * 16 + nb * 8 + 2 * tg;
        g_o[((size_t)b * LDIM + ir0) * CDIM + c0 * 8 + h]       = oacc[nb][0] * inv0;
        g_o[((size_t)b * LDIM + ir0) * CDIM + (c0 + 1) * 8 + h] = oacc[nb][1] * inv0;
        g_o[((size_t)b * LDIM + ir1) * CDIM + c0 * 8 + h]       = oacc[nb][2] * inv1;
        g_o[((size_t)b * LDIM + ir1) * CDIM + (c0 + 1) * 8 + h] = oacc[nb][3] * inv1;
    }
}

// ---------------------------------------------------------------------------
// Kernel 3: out via tf32 mma, operand-swapped; pipelined staging.
// ---------------------------------------------------------------------------
__global__ void __launch_bounds__(256) out_gemm(const float* __restrict__ w2,
                                                const float* __restrict__ b2,
                                                float* __restrict__ out) {
    __shared__ unsigned Ws[32][72];   // [k][n]
    __shared__ unsigned Os[64][36];   // [m][k]

    const int b  = blockIdx.z;
    const int m0 = blockIdx.x * 64;
    const int n0 = blockIdx.y * 64;
    const int t  = threadIdx.x;
    const int lane = t & 31;
    const int warp = t >> 5;
    const int wr = warp >> 1;
    const int wc = warp & 1;
    const int g  = lane >> 2;
    const int tg = lane & 3;

    const float* ob = g_o + (size_t)b * LDIM * CDIM;
    float acc[4][4] = {};

    const int w_kk = t >> 4, w_n4 = (t & 15) * 4;
    const int w_kk2 = w_kk + 16;
    const int o_mm = t >> 3, o_k4 = (t & 7) * 4;
    const int o_mm2 = o_mm + 32;

    float4 wR[2], oR[2];
    wR[0] = *(const float4*)&w2[(size_t)w_kk  * CDIM + n0 + w_n4];
    wR[1] = *(const float4*)&w2[(size_t)w_kk2 * CDIM + n0 + w_n4];
    oR[0] = *(const float4*)&ob[(size_t)(m0 + o_mm)  * CDIM + o_k4];
    oR[1] = *(const float4*)&ob[(size_t)(m0 + o_mm2) * CDIM + o_k4];

    for (int k0 = 0; k0 < CDIM; k0 += 32) {
        __syncthreads();
        st_tf4(&Ws[w_kk][w_n4],  wR[0]);
        st_tf4(&Ws[w_kk2][w_n4], wR[1]);
        st_tf4(&Os[o_mm][o_k4],  oR[0]);
        st_tf4(&Os[o_mm2][o_k4], oR[1]);
        if (k0 + 32 < CDIM) {
            int kn = k0 + 32;
            wR[0] = *(const float4*)&w2[(size_t)(kn + w_kk)  * CDIM + n0 + w_n4];
            wR[1] = *(const float4*)&w2[(size_t)(kn + w_kk2) * CDIM + n0 + w_n4];
            oR[0] = *(const float4*)&ob[(size_t)(m0 + o_mm)  * CDIM + kn + o_k4];
            oR[1] = *(const float4*)&ob[(size_t)(m0 + o_mm2) * CDIM + kn + o_k4];
        }
        __syncthreads();

        unsigned af[4][4];
        #pragma unroll
        for (int ks = 0; ks < 4; ks++) {
            af[ks][0] = Ws[ks * 8 + tg][wr * 16 + g];
            af[ks][1] = Ws[ks * 8 + tg][wr * 16 + g + 8];
            af[ks][2] = Ws[ks * 8 + tg + 4][wr * 16 + g];
            af[ks][3] = Ws[ks * 8 + tg + 4][wr * 16 + g + 8];
        }
        #pragma unroll
        for (int mb = 0; mb < 4; mb++) {
            int mc = wc * 32 + mb * 8 + g;
            #pragma unroll
            for (int ks = 0; ks < 4; ks++) {
                unsigned bf[2] = {Os[mc][ks * 8 + tg], Os[mc][ks * 8 + tg + 4]};
                mma8(acc[mb], af[ks], bf);
            }
        }
    }

    const int n_r0 = n0 + wr * 16 + g;
    const int n_r1 = n_r0 + 8;
    const float bias0 = b2[n_r0];
    const float bias1 = b2[n_r1];
    #pragma unroll
    for (int mb = 0; mb < 4; mb++) {
        int mA = m0 + wc * 32 + mb * 8 + 2 * tg;
        float2 v0 = {acc[mb][0] + bias0, acc[mb][1] + bias0};
        float2 v1 = {acc[mb][2] + bias1, acc[mb][3] + bias1};
        *(float2*)&out[((size_t)b * CDIM + n_r0) * LDIM + mA] = v0;
        *(float2*)&out[((size_t)b * CDIM + n_r1) * LDIM + mA] = v1;
    }
}

// ---------------------------------------------------------------------------
extern "C" void kernel_launch(void* const* d_in, const int* in_sizes, int n_in,
                              void* d_out, int out_size) {
    const float* x  = (const float*)d_in[0];
    const float* w1 = (const float*)d_in[1];
    const float* b1 = (const float*)d_in[2];
    const float* w2 = (const float*)d_in[3];
    const float* b2 = (const float*)d_in[4];
    float* out = (float*)d_out;

    qkv_gemm<<<dim3(LDIM / 64, N3C / 64, BSZ), 256>>>(x, w1, b1);
    attn_kernel<<<dim3(LDIM / 64, BSZ * HEADS), 256>>>();
    out_gemm<<<dim3(LDIM / 64, CDIM / 64, BSZ), 256>>>(w2, b2, out);
}

// round 6
// speedup vs baseline: 1.0085x; 1.0085x over previous
#include <cuda_runtime.h>
#include <math.h>

#define BSZ   2
#define CDIM  256
#define LDIM  4096
#define HEADS 8
#define HD    32
#define N3C   768

__device__ float g_q[BSZ*HEADS*LDIM*HD];
__device__ float g_k[BSZ*HEADS*LDIM*HD];
__device__ float g_v[BSZ*HEADS*LDIM*HD];
__device__ float g_o[BSZ*LDIM*CDIM];

__device__ __forceinline__ unsigned f2tf(float f) {
    unsigned r;
    asm("cvt.rna.tf32.f32 %0, %1;" : "=r"(r) : "f"(f));
    return r;
}

__device__ __forceinline__ void mma8(float* c, const unsigned* a, const unsigned* b) {
    asm volatile(
        "mma.sync.aligned.m16n8k8.row.col.f32.tf32.tf32.f32 "
        "{%0,%1,%2,%3},{%4,%5,%6,%7},{%8,%9},{%0,%1,%2,%3};"
        : "+f"(c[0]), "+f"(c[1]), "+f"(c[2]), "+f"(c[3])
        : "r"(a[0]), "r"(a[1]), "r"(a[2]), "r"(a[3]), "r"(b[0]), "r"(b[1]));
}

__device__ __forceinline__ void st_tf4(unsigned* dst, float4 v) {
    unsigned u[4] = {f2tf(v.x), f2tf(v.y), f2tf(v.z), f2tf(v.w)};
    *(uint4*)dst = *(uint4*)u;
}

// ---------------------------------------------------------------------------
// Kernel 1: qkv via tf32 mma, operand-swapped; 2-stage smem double buffer,
// one __syncthreads per K-chunk.
// ---------------------------------------------------------------------------
__global__ void __launch_bounds__(256) qkv_gemm(const float* __restrict__ x,
                                                const float* __restrict__ w1,
                                                const float* __restrict__ b1) {
    __shared__ unsigned Ws[2][32][72];   // [stage][k][n]
    __shared__ unsigned Xs[2][32][72];   // [stage][k][m]

    const int b  = blockIdx.z;
    const int m0 = blockIdx.x * 64;
    const int n0 = blockIdx.y * 64;
    const int t  = threadIdx.x;
    const int lane = t & 31;
    const int warp = t >> 5;
    const int wr = warp >> 1;
    const int wc = warp & 1;
    const int g  = lane >> 2;
    const int tg = lane & 3;

    const float* xb = x + (size_t)b * CDIM * LDIM;
    float acc[4][4] = {};

    const int s_kk = t >> 4, s_c4 = (t & 15) * 4;
    const int s_kk2 = s_kk + 16;

    float4 wR[2], xR[2];
    // chunk 0 -> regs -> stage 0
    wR[0] = *(const float4*)&w1[(size_t)s_kk  * N3C + n0 + s_c4];
    wR[1] = *(const float4*)&w1[(size_t)s_kk2 * N3C + n0 + s_c4];
    xR[0] = *(const float4*)&xb[(size_t)s_kk  * LDIM + m0 + s_c4];
    xR[1] = *(const float4*)&xb[(size_t)s_kk2 * LDIM + m0 + s_c4];
    st_tf4(&Ws[0][s_kk][s_c4],  wR[0]);
    st_tf4(&Ws[0][s_kk2][s_c4], wR[1]);
    st_tf4(&Xs[0][s_kk][s_c4],  xR[0]);
    st_tf4(&Xs[0][s_kk2][s_c4], xR[1]);
    // chunk 1 -> regs
    wR[0] = *(const float4*)&w1[(size_t)(32 + s_kk)  * N3C + n0 + s_c4];
    wR[1] = *(const float4*)&w1[(size_t)(32 + s_kk2) * N3C + n0 + s_c4];
    xR[0] = *(const float4*)&xb[(size_t)(32 + s_kk)  * LDIM + m0 + s_c4];
    xR[1] = *(const float4*)&xb[(size_t)(32 + s_kk2) * LDIM + m0 + s_c4];
    __syncthreads();

    #pragma unroll
    for (int i = 0; i < 8; i++) {
        const int cur = i & 1;
        unsigned af[4][4];
        #pragma unroll
        for (int ks = 0; ks < 4; ks++) {
            af[ks][0] = Ws[cur][ks * 8 + tg][wr * 16 + g];
            af[ks][1] = Ws[cur][ks * 8 + tg][wr * 16 + g + 8];
            af[ks][2] = Ws[cur][ks * 8 + tg + 4][wr * 16 + g];
            af[ks][3] = Ws[cur][ks * 8 + tg + 4][wr * 16 + g + 8];
        }
        #pragma unroll
        for (int mb = 0; mb < 4; mb++) {
            int mc = wc * 32 + mb * 8 + g;
            #pragma unroll
            for (int ks = 0; ks < 4; ks++) {
                unsigned bf[2] = {Xs[cur][ks * 8 + tg][mc], Xs[cur][ks * 8 + tg + 4][mc]};
                mma8(acc[mb], af[ks], bf);
            }
        }
        if (i < 7) {
            const int nxt = 1 - cur;
            st_tf4(&Ws[nxt][s_kk][s_c4],  wR[0]);
            st_tf4(&Ws[nxt][s_kk2][s_c4], wR[1]);
            st_tf4(&Xs[nxt][s_kk][s_c4],  xR[0]);
            st_tf4(&Xs[nxt][s_kk2][s_c4], xR[1]);
            if (i < 6) {
                int kn = (i + 2) * 32;
                wR[0] = *(const float4*)&w1[(size_t)(kn + s_kk)  * N3C + n0 + s_c4];
                wR[1] = *(const float4*)&w1[(size_t)(kn + s_kk2) * N3C + n0 + s_c4];
                xR[0] = *(const float4*)&xb[(size_t)(kn + s_kk)  * LDIM + m0 + s_c4];
                xR[1] = *(const float4*)&xb[(size_t)(kn + s_kk2) * LDIM + m0 + s_c4];
            }
            __syncthreads();
        }
    }

    const float inv_scale = 0.1767766952966368811f;
    const int n_r0 = n0 + wr * 16 + g;
    const int n_r1 = n_r0 + 8;
    const int k3_0 = n_r0 % 3, h_0 = (n_r0 / 3) & 7, c_0 = n_r0 / 24;
    const int k3_1 = n_r1 % 3, h_1 = (n_r1 / 3) & 7, c_1 = n_r1 / 24;
    const float bias0 = b1[n_r0], bias1 = b1[n_r1];
    float* dst0 = (k3_0 == 0) ? g_q : (k3_0 == 1) ? g_k : g_v;
    float* dst1 = (k3_1 == 0) ? g_q : (k3_1 == 1) ? g_k : g_v;
    const float sc0 = (k3_0 == 0) ? inv_scale : 1.f;
    const float sc1 = (k3_1 == 0) ? inv_scale : 1.f;
    const size_t base0 = (size_t)(b * HEADS + h_0) * LDIM;
    const size_t base1 = (size_t)(b * HEADS + h_1) * LDIM;
    #pragma unroll
    for (int mb = 0; mb < 4; mb++) {
        int mA = m0 + wc * 32 + mb * 8 + 2 * tg;
        dst0[(base0 + mA)     * HD + c_0] = (acc[mb][0] + bias0) * sc0;
        dst0[(base0 + mA + 1) * HD + c_0] = (acc[mb][1] + bias0) * sc0;
        dst1[(base1 + mA)     * HD + c_1] = (acc[mb][2] + bias1) * sc1;
        dst1[(base1 + mA + 1) * HD + c_1] = (acc[mb][3] + bias1) * sc1;
    }
}

// ---------------------------------------------------------------------------
// Kernel 2: banded attention. S via tf32 mma; P moved to PV A-fragments by
// intra-quad shuffles (no smem round-trip, 2 syncs/tile). Each warp does PV
// over its 32-key half across all 32 channels; wc-pair O summed once at end.
// ---------------------------------------------------------------------------
__global__ void __launch_bounds__(256) attn_kernel() {
    __shared__ unsigned Qs[64][36];
    __shared__ unsigned Ks[64][36];
    __shared__ unsigned Vs[64][40];
    __shared__ float    Red[64][33];
    __shared__ float    Lsm[64][2];

    const int qt = blockIdx.x;
    const int bh = blockIdx.y;
    const int i0 = qt * 64;
    const int t  = threadIdx.x;
    const int lane = t & 31;
    const int warp = t >> 5;
    const int wr = warp >> 1;
    const int wc = warp & 1;
    const int g  = lane >> 2;
    const int tg = lane & 3;

    const float* qb = g_q + (size_t)bh * LDIM * HD;
    const float* kb = g_k + (size_t)bh * LDIM * HD;
    const float* vb = g_v + (size_t)bh * LDIM * HD;

    const int s_row0 = t >> 3, s_c4 = (t & 7) * 4;
    const int s_row1 = s_row0 + 32;

    st_tf4(&Qs[s_row0][s_c4], *(const float4*)&qb[(size_t)(i0 + s_row0) * HD + s_c4]);
    st_tf4(&Qs[s_row1][s_c4], *(const float4*)&qb[(size_t)(i0 + s_row1) * HD + s_c4]);

    const bool hasG = (qt == 0) || (qt == 63);
    const int  tlo  = max(0, i0 - 512) >> 6;
    const int  thi  = min(LDIM - 1, i0 + 63 + 512) >> 6;
    const int  lead  = (tlo > 0) ? 1 : 0;
    const int  trail = (thi < 63) ? 1 : 0;
    const int  nband = thi - tlo + 1;
    const int  cnt   = hasG ? 64 : (nband + lead + trail);

    int t0 = hasG ? 0 : (lead ? 0 : tlo);
    float4 kR[2], vR[2];
    {
        const int j0 = t0 * 64;
        kR[0] = *(const float4*)&kb[(size_t)(j0 + s_row0) * HD + s_c4];
        kR[1] = *(const float4*)&kb[(size_t)(j0 + s_row1) * HD + s_c4];
        vR[0] = *(const float4*)&vb[(size_t)(j0 + s_row0) * HD + s_c4];
        vR[1] = *(const float4*)&vb[(size_t)(j0 + s_row1) * HD + s_c4];
    }
    __syncthreads();

    unsigned af[4][4];
    const int r0 = wr * 16 + g;
    const int r1 = r0 + 8;
    #pragma unroll
    for (int ks = 0; ks < 4; ks++) {
        af[ks][0] = Qs[r0][ks * 8 + tg];
        af[ks][1] = Qs[r1][ks * 8 + tg];
        af[ks][2] = Qs[r0][ks * 8 + tg + 4];
        af[ks][3] = Qs[r1][ks * 8 + tg + 4];
    }

    const int ir0 = i0 + r0, ir1 = i0 + r1;
    const bool ig0 = (ir0 == 0) || (ir0 == 63) || (ir0 == 4032) || (ir0 == 4095);
    const bool ig1 = (ir1 == 0) || (ir1 == 63) || (ir1 == 4032) || (ir1 == 4095);

    float oacc[4][4] = {};                 // output col-block nb2 (8 cols each)
    float ls0 = 0.f, ls1 = 0.f;
    int tcur = t0;
    const int shA = (lane & ~3) | (tg >> 1);   // src lane for cols tg
    const int shB = shA + 2;                   // src lane for cols tg+4
    const bool odd = tg & 1;

    for (int it = 0; it < cnt; it++) {
        const int j0 = tcur * 64;

        __syncthreads();                   // prev PV (Vs reads) done
        st_tf4(&Ks[s_row0][s_c4], kR[0]);
        st_tf4(&Ks[s_row1][s_c4], kR[1]);
        st_tf4(&Vs[s_row0][s_c4], vR[0]);
        st_tf4(&Vs[s_row1][s_c4], vR[1]);
        if (it + 1 < cnt) {
            int nx = it + 1;
            int tnext;
            if (hasG) tnext = nx;
            else {
                int j = nx - lead;
                tnext = (nx == 0 && lead) ? 0 : ((j < nband) ? (tlo + j) : 63);
            }
            const int jn = tnext * 64;
            kR[0] = *(const float4*)&kb[(size_t)(jn + s_row0) * HD + s_c4];
            kR[1] = *(const float4*)&kb[(size_t)(jn + s_row1) * HD + s_c4];
            vR[0] = *(const float4*)&vb[(size_t)(jn + s_row0) * HD + s_c4];
            vR[1] = *(const float4*)&vb[(size_t)(jn + s_row1) * HD + s_c4];
            tcur = tnext;
        }
        __syncthreads();

        // S = Q @ K^T (warp: 16 rows x 32 keys)
        float sacc[4][4] = {};
        #pragma unroll
        for (int nb = 0; nb < 4; nb++) {
            int jn = wc * 32 + nb * 8 + g;
            #pragma unroll
            for (int ks = 0; ks < 4; ks++) {
                unsigned bf[2] = {Ks[jn][ks * 8 + tg], Ks[jn][ks * 8 + tg + 4]};
                mma8(sacc[nb], af[ks], bf);
            }
        }

        // mask + exp + cvt (accumulator layout), accumulate row sums
        unsigned pt[4][4];
        #pragma unroll
        for (int nb = 0; nb < 4; nb++) {
            int jb = j0 + wc * 32 + nb * 8 + 2 * tg;
            int jb1 = jb + 1;
            bool jg0 = (jb == 0) || (jb == 63) || (jb == 4032) || (jb == 4095);
            bool jg1 = (jb1 == 0) || (jb1 == 63) || (jb1 == 4032) || (jb1 == 4095);
            int d00 = ir0 - jb, d01 = ir0 - jb1, d10 = ir1 - jb, d11 = ir1 - jb1;
            float p0 = (ig0 || jg0 || (d00 <= 512 && d00 >= -512)) ? __expf(sacc[nb][0]) : 0.f;
            float p1 = (ig0 || jg1 || (d01 <= 512 && d01 >= -512)) ? __expf(sacc[nb][1]) : 0.f;
            float p2 = (ig1 || jg0 || (d10 <= 512 && d10 >= -512)) ? __expf(sacc[nb][2]) : 0.f;
            float p3 = (ig1 || jg1 || (d11 <= 512 && d11 >= -512)) ? __expf(sacc[nb][3]) : 0.f;
            pt[nb][0] = f2tf(p0); pt[nb][1] = f2tf(p1);
            pt[nb][2] = f2tf(p2); pt[nb][3] = f2tf(p3);
            ls0 += __uint_as_float(pt[nb][0]) + __uint_as_float(pt[nb][1]);
            ls1 += __uint_as_float(pt[nb][2]) + __uint_as_float(pt[nb][3]);
        }

        // PV over this warp's 32-key half, all 32 channels.
        #pragma unroll
        for (int ks = 0; ks < 4; ks++) {
            unsigned e0 = __shfl_sync(~0u, pt[ks][0], shA);
            unsigned e1 = __shfl_sync(~0u, pt[ks][1], shA);
            unsigned e2 = __shfl_sync(~0u, pt[ks][2], shA);
            unsigned e3 = __shfl_sync(~0u, pt[ks][3], shA);
            unsigned f0 = __shfl_sync(~0u, pt[ks][0], shB);
            unsigned f1 = __shfl_sync(~0u, pt[ks][1], shB);
            unsigned f2 = __shfl_sync(~0u, pt[ks][2], shB);
            unsigned f3 = __shfl_sync(~0u, pt[ks][3], shB);
            unsigned pa[4];
            pa[0] = odd ? e1 : e0;   // row g,   col tg
            pa[1] = odd ? e3 : e2;   // row g+8, col tg
            pa[2] = odd ? f1 : f0;   // row g,   col tg+4
            pa[3] = odd ? f3 : f2;   // row g+8, col tg+4
            const int vrow0 = wc * 32 + ks * 8 + tg;
            #pragma unroll
            for (int nb2 = 0; nb2 < 4; nb2++) {
                int cn = nb2 * 8 + g;
                unsigned vf[2] = {Vs[vrow0][cn], Vs[vrow0 + 4][cn]};
                mma8(oacc[nb2], pa, vf);
            }
        }
    }

    // row-sum reduction over tg, publish per-wc partial
    ls0 += __shfl_xor_sync(~0u, ls0, 1); ls0 += __shfl_xor_sync(~0u, ls0, 2);
    ls1 += __shfl_xor_sync(~0u, ls1, 1); ls1 += __shfl_xor_sync(~0u, ls1, 2);
    if (tg == 0) { Lsm[r0][wc] = ls0; Lsm[r1][wc] = ls1; }
    // wc=1 publishes its partial O
    if (wc == 1) {
        #pragma unroll
        for (int nb2 = 0; nb2 < 4; nb2++) {
            int c0 = nb2 * 8 + 2 * tg;
            Red[r0][c0] = oacc[nb2][0]; Red[r0][c0 + 1] = oacc[nb2][1];
            Red[r1][c0] = oacc[nb2][2]; Red[r1][c0 + 1] = oacc[nb2][3];
        }
    }
    __syncthreads();

    if (wc == 0) {
        float inv0 = 1.f / (Lsm[r0][0] + Lsm[r0][1]);
        float inv1 = 1.f / (Lsm[r1][0] + Lsm[r1][1]);
        const int b = bh >> 3, h = bh & 7;
        #pragma unroll
        for (int nb2 = 0; nb2 < 4; nb2++) {
            int c0 = nb2 * 8 + 2 * tg;
            float o0 = (oacc[nb2][0] + Red[r0][c0])     * inv0;
            float o1 = (oacc[nb2][1] + Red[r0][c0 + 1]) * inv0;
            float o2 = (oacc[nb2][2] + Red[r1][c0])     * inv1;
            float o3 = (oacc[nb2][3] + Red[r1][c0 + 1]) * inv1;
            g_o[((size_t)b * LDIM + ir0) * CDIM + c0 * 8 + h]       = o0;
            g_o[((size_t)b * LDIM + ir0) * CDIM + (c0 + 1) * 8 + h] = o1;
            g_o[((size_t)b * LDIM + ir1) * CDIM + c0 * 8 + h]       = o2;
            g_o[((size_t)b * LDIM + ir1) * CDIM + (c0 + 1) * 8 + h] = o3;
        }
    }
}

// ---------------------------------------------------------------------------
// Kernel 3: out via tf32 mma; 2-stage smem double buffer, one sync per chunk.
// ---------------------------------------------------------------------------
__global__ void __launch_bounds__(256) out_gemm(const float* __restrict__ w2,
                                                const float* __restrict__ b2,
                                                float* __restrict__ out) {
    __shared__ unsigned Ws[2][32][72];   // [stage][k][n]
    __shared__ unsigned Os[2][64][36];   // [stage][m][k]

    const int b  = blockIdx.z;
    const int m0 = blockIdx.x * 64;
    const int n0 = blockIdx.y * 64;
    const int t  = threadIdx.x;
    const int lane = t & 31;
    const int warp = t >> 5;
    const int wr = warp >> 1;
    const int wc = warp & 1;
    const int g  = lane >> 2;
    const int tg = lane & 3;

    const float* ob = g_o + (size_t)b * LDIM * CDIM;
    float acc[4][4] = {};

    const int w_kk = t >> 4, w_n4 = (t & 15) * 4;
    const int w_kk2 = w_kk + 16;
    const int o_mm = t >> 3, o_k4 = (t & 7) * 4;
    const int o_mm2 = o_mm + 32;

    float4 wR[2], oR[2];
    wR[0] = *(const float4*)&w2[(size_t)w_kk  * CDIM + n0 + w_n4];
    wR[1] = *(const float4*)&w2[(size_t)w_kk2 * CDIM + n0 + w_n4];
    oR[0] = *(const float4*)&ob[(size_t)(m0 + o_mm)  * CDIM + o_k4];
    oR[1] = *(const float4*)&ob[(size_t)(m0 + o_mm2) * CDIM + o_k4];
    st_tf4(&Ws[0][w_kk][w_n4],  wR[0]);
    st_tf4(&Ws[0][w_kk2][w_n4], wR[1]);
    st_tf4(&Os[0][o_mm][o_k4],  oR[0]);
    st_tf4(&Os[0][o_mm2][o_k4], oR[1]);
    wR[0] = *(const float4*)&w2[(size_t)(32 + w_kk)  * CDIM + n0 + w_n4];
    wR[1] = *(const float4*)&w2[(size_t)(32 + w_kk2) * CDIM + n0 + w_n4];
    oR[0] = *(const float4*)&ob[(size_t)(m0 + o_mm)  * CDIM + 32 + o_k4];
    oR[1] = *(const float4*)&ob[(size_t)(m0 + o_mm2) * CDIM + 32 + o_k4];
    __syncthreads();

    #pragma unroll
    for (int i = 0; i < 8; i++) {
        const int cur = i & 1;
        unsigned af[4][4];
        #pragma unroll
        for (int ks = 0; ks < 4; ks++) {
            af[ks][0] = Ws[cur][ks * 8 + tg][wr * 16 + g];
            af[ks][1] = Ws[cur][ks * 8 + tg][wr * 16 + g + 8];
            af[ks][2] = Ws[cur][ks * 8 + tg + 4][wr * 16 + g];
            af[ks][3] = Ws[cur][ks * 8 + tg + 4][wr * 16 + g + 8];
        }
        #pragma unroll
        for (int mb = 0; mb < 4; mb++) {
            int mc = wc * 32 + mb * 8 + g;
            #pragma unroll
            for (int ks = 0; ks < 4; ks++) {
                unsigned bf[2] = {Os[cur][mc][ks * 8 + tg], Os[cur][mc][ks * 8 + tg + 4]};
                mma8(acc[mb], af[ks], bf);
            }
        }
        if (i < 7) {
            const int nxt = 1 - cur;
            st_tf4(&Ws[nxt][w_kk][w_n4],  wR[0]);
            st_tf4(&Ws[nxt][w_kk2][w_n4], wR[1]);
            st_tf4(&Os[nxt][o_mm][o_k4],  oR[0]);
            st_tf4(&Os[nxt][o_mm2][o_k4], oR[1]);
            if (i < 6) {
                int kn = (i + 2) * 32;
                wR[0] = *(const float4*)&w2[(size_t)(kn + w_kk)  * CDIM + n0 + w_n4];
                wR[1] = *(const float4*)&w2[(size_t)(kn + w_kk2) * CDIM + n0 + w_n4];
                oR[0] = *(const float4*)&ob[(size_t)(m0 + o_mm)  * CDIM + kn + o_k4];
                oR[1] = *(const float4*)&ob[(size_t)(m0 + o_mm2) * CDIM + kn + o_k4];
            }
            __syncthreads();
        }
    }

    const int n_r0 = n0 + wr * 16 + g;
    const int n_r1 = n_r0 + 8;
    const float bias0 = b2[n_r0];
    const float bias1 = b2[n_r1];
    #pragma unroll
    for (int mb = 0; mb < 4; mb++) {
        int mA = m0 + wc * 32 + mb * 8 + 2 * tg;
        float2 v0 = {acc[mb][0] + bias0, acc[mb][1] + bias0};
        float2 v1 = {acc[mb][2] + bias1, acc[mb][3] + bias1};
        *(float2*)&out[((size_t)b * CDIM + n_r0) * LDIM + mA] = v0;
        *(float2*)&out[((size_t)b * CDIM + n_r1) * LDIM + mA] = v1;
    }
}

// ---------------------------------------------------------------------------
extern "C" void kernel_launch(void* const* d_in, const int* in_sizes, int n_in,
                              void* d_out, int out_size) {
    const float* x  = (const float*)d_in[0];
    const float* w1 = (const float*)d_in[1];
    const float* b1 = (const float*)d_in[2];
    const float* w2 = (const float*)d_in[3];
    const float* b2 = (const float*)d_in[4];
    float* out = (float*)d_out;

    qkv_gemm<<<dim3(LDIM / 64, N3C / 64, BSZ), 256>>>(x, w1, b1);
    attn_kernel<<<dim3(LDIM / 64, BSZ * HEADS), 256>>>();
    out_gemm<<<dim3(LDIM / 64, CDIM / 64, BSZ), 256>>>(w2, b2, out);
}